// round 2
// baseline (speedup 1.0000x reference)
#include <cuda_runtime.h>
#include <math.h>

// Problem constants
#define NB 32
#define ND 96
#define NL 2304   // 48*48
#define NH 48
#define NW 48
#define NK 2
#define NN 16
#define NR 6
#define NCDB 38   // NR + 2*NN
#define CENTER 1176  // 24*48+24

// ---------------- device scratch (no allocations allowed) ----------------
__device__ float g_xfeat [NB*ND*NL];
__device__ float g_xconv [NB*ND*NL];
__device__ float g_xconvT[NB*NL*ND];
__device__ float g_sim   [NB*NL];
__device__ int   g_sortidx[NB*NL];
__device__ float g_xsorted[NB*NL*ND];
__device__ float g_dtbc  [(size_t)NB*NK*NL*128]; // per (b,k,p): dt[0:96], B[96:112], C[112:128]
__device__ float g_y0    [NB*NL*ND];
__device__ float g_y1    [NB*NL*ND];
__device__ float g_mamT  [NB*NL*ND];
__device__ float g_lc    [NB*ND*NL];
__device__ float g_lcT   [NB*NL*ND];
__device__ float g_tT    [NB*ND*NL];
__device__ float g_psum  [NB*ND];
__device__ float g_psum2 [NB*ND];
__device__ float g_bnscale[ND];
__device__ float g_bnshift[ND];

// ---------------- K1: in_proj GEMM: xfeat[b,d,l] = sum_c W[d,c]*x[b,c,l] + bias[d]
__global__ void k_inproj(const float* __restrict__ x, const float* __restrict__ w,
                         const float* __restrict__ bias) {
    __shared__ float shx[32*132];
    __shared__ float shw[32*96];
    int b = blockIdx.y, l0 = blockIdx.x * 128, tid = threadIdx.x;
    int tx = tid & 15, ty = tid >> 4;
    int db = ty * 6, lb = tx * 8;
    float acc[6][8];
#pragma unroll
    for (int i = 0; i < 6; i++)
#pragma unroll
        for (int j = 0; j < 8; j++) acc[i][j] = 0.f;
    for (int kc = 0; kc < ND; kc += 32) {
        for (int i = tid; i < 32*128; i += 256) {
            int cc = i >> 7, li = i & 127;
            shx[cc*132 + li] = x[(size_t)(b*ND + kc + cc)*NL + l0 + li];
        }
        for (int i = tid; i < 32*96; i += 256) {
            int dloc = i % 96, cl = i / 96;
            shw[cl*96 + dloc] = w[dloc*ND + kc + cl];
        }
        __syncthreads();
        for (int c = 0; c < 32; c++) {
            float xv[8];
            const float4* xr = (const float4*)&shx[c*132 + lb];
            float4 a0 = xr[0], a1 = xr[1];
            xv[0]=a0.x; xv[1]=a0.y; xv[2]=a0.z; xv[3]=a0.w;
            xv[4]=a1.x; xv[5]=a1.y; xv[6]=a1.z; xv[7]=a1.w;
#pragma unroll
            for (int i = 0; i < 6; i++) {
                float wv = shw[c*96 + db + i];
#pragma unroll
                for (int j = 0; j < 8; j++) acc[i][j] = fmaf(wv, xv[j], acc[i][j]);
            }
        }
        __syncthreads();
    }
#pragma unroll
    for (int i = 0; i < 6; i++) {
        float bv = bias[db + i];
#pragma unroll
        for (int j = 0; j < 8; j++)
            g_xfeat[(size_t)(b*ND + db + i)*NL + l0 + lb + j] = acc[i][j] + bv;
    }
}

// ---------------- K2: depthwise 3x3 SAME + bias + SiLU -> g_xconv
__global__ void k_dwconv(const float* __restrict__ w, const float* __restrict__ bias) {
    __shared__ float plane[NL];
    int bd = blockIdx.x;
    int d = bd % ND;
    int tid = threadIdx.x;
    const float* src = g_xfeat + (size_t)bd*NL;
    for (int i = tid; i < NL; i += 256) plane[i] = src[i];
    float w9[9];
#pragma unroll
    for (int t = 0; t < 9; t++) w9[t] = w[d*9 + t];
    float bv = bias[d];
    __syncthreads();
    float* dst = g_xconv + (size_t)bd*NL;
    for (int l = tid; l < NL; l += 256) {
        int hh = l / NW, ww = l - hh*NW;
        float acc = bv;
#pragma unroll
        for (int di = 0; di < 3; di++) {
            int h2 = hh + di - 1;
            if (h2 < 0 || h2 >= NH) continue;
#pragma unroll
            for (int dj = 0; dj < 3; dj++) {
                int w2 = ww + dj - 1;
                if (w2 < 0 || w2 >= NW) continue;
                acc = fmaf(plane[h2*NW + w2], w9[di*3 + dj], acc);
            }
        }
        dst[l] = acc / (1.f + __expf(-acc));
    }
}

// ---------------- K3: transpose xconv (b,D,L) -> xconvT (b,L,D). grid (72,3,32) blk (32,8)
__global__ void k_trans_xconv() {
    __shared__ float tile[32][33];
    int b = blockIdx.z, d0 = blockIdx.y*32, l0 = blockIdx.x*32;
    int tx = threadIdx.x, ty = threadIdx.y;
    for (int r = ty; r < 32; r += 8)
        tile[r][tx] = g_xconv[(size_t)(b*ND + d0 + r)*NL + l0 + tx];
    __syncthreads();
    for (int r = ty; r < 32; r += 8)
        g_xconvT[((size_t)b*NL + l0 + r)*ND + d0 + tx] = tile[tx][r];
}

// ---------------- K4: cosine similarity to center pixel. grid (32,36), 256 thr
__global__ void k_sim() {
    __shared__ float cf[ND];
    int b = blockIdx.x, tid = threadIdx.x;
    if (tid < ND) cf[tid] = g_xconvT[((size_t)b*NL + CENTER)*ND + tid];
    __syncthreads();
    int lane = tid & 31, wid = tid >> 5;
    float c0 = cf[lane], c1 = cf[lane+32], c2 = cf[lane+64];
    float nc = c0*c0 + c1*c1 + c2*c2;
#pragma unroll
    for (int o = 16; o > 0; o >>= 1) nc += __shfl_xor_sync(0xffffffffu, nc, o);
    float rc = 1.f / fmaxf(sqrtf(nc), 1e-12f);
    for (int r = 0; r < 8; r++) {
        int l = blockIdx.y*64 + wid*8 + r;
        const float* row = g_xconvT + ((size_t)b*NL + l)*ND;
        float x0 = row[lane], x1 = row[lane+32], x2 = row[lane+64];
        float dot = x0*c0 + x1*c1 + x2*c2;
        float nx  = x0*x0 + x1*x1 + x2*x2;
#pragma unroll
        for (int o = 16; o > 0; o >>= 1) {
            dot += __shfl_xor_sync(0xffffffffu, dot, o);
            nx  += __shfl_xor_sync(0xffffffffu, nx,  o);
        }
        if (lane == 0)
            g_sim[b*NL + l] = dot * rc / fmaxf(sqrtf(nx), 1e-12f);
    }
}

// ---------------- K5: per-batch stable argsort (desc sim, tie: idx asc). bitonic 4096
__global__ void k_sort() {
    __shared__ float sk[4096];
    __shared__ int   sv[4096];
    int b = blockIdx.x, tid = threadIdx.x;
    float ninf = -__int_as_float(0x7f800000);
    for (int i = tid; i < 4096; i += 1024) {
        sk[i] = (i < NL) ? g_sim[b*NL + i] : ninf;
        sv[i] = i;
    }
    for (int size = 2; size <= 4096; size <<= 1) {
        for (int stride = size >> 1; stride > 0; stride >>= 1) {
            __syncthreads();
            for (int t = tid; t < 2048; t += 1024) {
                int low = t & (stride - 1);
                int i = ((t - low) << 1) + low;
                int j = i + stride;
                float ki = sk[i], kj = sk[j];
                int vi = sv[i], vj = sv[j];
                bool jFirst = (kj > ki) || (kj == ki && vj < vi);
                bool up = (i & size) == 0;
                if (up ? jFirst : !jFirst) {
                    sk[i] = kj; sk[j] = ki; sv[i] = vj; sv[j] = vi;
                }
            }
        }
    }
    __syncthreads();
    for (int i = tid; i < NL; i += 1024) g_sortidx[b*NL + i] = sv[i];
}

// ---------------- K6: gather x_sorted + projections dt(softplus)/B/C. grid (144,32), 256 thr
__global__ void k_prep(const float* __restrict__ xpw, const float* __restrict__ dtw,
                       const float* __restrict__ dtb) {
    __shared__ __align__(16) float s_xpw[NK*NCDB*ND];   // 7296
    __shared__ float s_dtw[NK*ND*NR];                   // 1152
    __shared__ float s_dtb[NK*ND];
    __shared__ __align__(16) float s_x[16*ND];          // 1536
    __shared__ float s_xdbl[16*NK*NCDB];                // 1216
    __shared__ int s_srt[16];
    int b = blockIdx.y, p0 = blockIdx.x*16, tid = threadIdx.x;
    for (int i = tid; i < NK*NCDB*ND; i += 256) s_xpw[i] = xpw[i];
    for (int i = tid; i < NK*ND*NR;  i += 256) s_dtw[i] = dtw[i];
    for (int i = tid; i < NK*ND;     i += 256) s_dtb[i] = dtb[i];
    if (tid < 16) s_srt[tid] = g_sortidx[b*NL + p0 + tid];
    __syncthreads();
    for (int i = tid; i < 16*ND; i += 256) {
        int p = i / ND, dd = i - p*ND;
        float v = g_xconvT[((size_t)b*NL + s_srt[p])*ND + dd];
        s_x[i] = v;
        g_xsorted[((size_t)b*NL + p0 + p)*ND + dd] = v;
    }
    __syncthreads();
    for (int i = tid; i < 16*NK*NCDB; i += 256) {
        int p = i / (NK*NCDB); int rem = i - p*(NK*NCDB);
        int k = rem / NCDB; int c = rem - k*NCDB;
        const float4* xr = (const float4*)&s_x[p*ND];
        const float4* wr = (const float4*)&s_xpw[(k*NCDB + c)*ND];
        float acc = 0.f;
#pragma unroll
        for (int q = 0; q < ND/4; q++) {
            float4 a = xr[q], bq = wr[q];
            acc += a.x*bq.x + a.y*bq.y + a.z*bq.z + a.w*bq.w;
        }
        s_xdbl[i] = acc;
        if (c >= NR)
            g_dtbc[(((size_t)(b*NK + k)*NL) + p0 + p)*128 + 96 + (c - NR)] = acc;
    }
    __syncthreads();
    for (int i = tid; i < 16*NK*ND; i += 256) {
        int p = i / (NK*ND); int rem = i - p*(NK*ND);
        int k = rem / ND; int dd = rem - k*ND;
        float acc = s_dtb[k*ND + dd];
        const float* xd = &s_xdbl[(p*NK + k)*NCDB];
        const float* wv = &s_dtw[(k*ND + dd)*NR];
#pragma unroll
        for (int r = 0; r < NR; r++) acc = fmaf(xd[r], wv[r], acc);
        float sp = (acc > 20.f) ? acc : log1pf(expf(acc));
        g_dtbc[(((size_t)(b*NK + k)*NL) + p0 + p)*128 + dd] = sp;
    }
}

// ---------------- K7: selective scan. 128 blocks = (b,k,d-half), 384 threads.
__global__ void __launch_bounds__(384) k_scan(const float* __restrict__ A_logs) {
    __shared__ float s_dtbc[8*128];
    __shared__ float s_x[8*96];
    int blk = blockIdx.x;
    int g = blk & 1, k = (blk >> 1) & 1, b = blk >> 2;
    int tid = threadIdx.x;
    int dd = tid >> 3, ng = tid & 7, n0 = ng*2;
    int d = g*48 + dd;
    float A0 = -expf(A_logs[(k*ND + d)*NN + n0]);
    float A1 = -expf(A_logs[(k*ND + d)*NN + n0 + 1]);
    float h0 = 0.f, h1 = 0.f;
    const float* dtbc = g_dtbc + (size_t)(b*NK + k)*NL*128;
    const float* xs   = g_xsorted + (size_t)b*NL*ND;
    float* yo = ((k == 0) ? g_y0 : g_y1) + (size_t)b*NL*ND;
    for (int c0 = 0; c0 < NL; c0 += 8) {
        for (int i = tid; i < 1024; i += 384) {
            int j = i >> 7, t = i & 127;
            int p = (k == 0) ? (c0 + j) : (NL - 1 - c0 - j);
            s_dtbc[i] = dtbc[(size_t)p*128 + t];
        }
        for (int i = tid; i < 768; i += 384) {
            int j = i / 96, t = i - j*96;
            int p = (k == 0) ? (c0 + j) : (NL - 1 - c0 - j);
            s_x[i] = xs[(size_t)p*96 + t];
        }
        __syncthreads();
#pragma unroll
        for (int j = 0; j < 8; j++) {
            float dt = s_dtbc[j*128 + d];
            float xv = s_x[j*96 + d];
            float B0 = s_dtbc[j*128 + 96  + n0], B1 = s_dtbc[j*128 + 97  + n0];
            float C0 = s_dtbc[j*128 + 112 + n0], C1 = s_dtbc[j*128 + 113 + n0];
            float u = dt * xv;
            h0 = fmaf(__expf(dt*A0), h0, u*B0);
            h1 = fmaf(__expf(dt*A1), h1, u*B1);
            float yp = h0*C0 + h1*C1;
            yp += __shfl_xor_sync(0xffffffffu, yp, 4);
            yp += __shfl_xor_sync(0xffffffffu, yp, 2);
            yp += __shfl_xor_sync(0xffffffffu, yp, 1);
            if (ng == 0) {
                int p = (k == 0) ? (c0 + j) : (NL - 1 - c0 - j);
                yo[(size_t)p*96 + d] = yp;
            }
        }
        __syncthreads();
    }
}

// ---------------- K8: combine fwd+rev + D*x, scatter to unsorted channel-last. grid (144,32)
__global__ void k_combine(const float* __restrict__ Ds) {
    __shared__ int sidx[16];
    int b = blockIdx.y, p0 = blockIdx.x*16, tid = threadIdx.x;
    if (tid < 16) sidx[tid] = g_sortidx[b*NL + p0 + tid];
    __syncthreads();
    for (int i = tid; i < 16*ND; i += 256) {
        int pl = i / ND, d = i - pl*ND;
        size_t src = ((size_t)b*NL + p0 + pl)*ND + d;
        float v = g_y0[src] + g_y1[src] + (Ds[d] + Ds[ND + d]) * g_xsorted[src];
        g_mamT[((size_t)b*NL + sidx[pl])*ND + d] = v;
    }
}

// ---------------- K9: local conv branch: dwconv + bias, write lc, partial BN sums
__global__ void k_localconv(const float* __restrict__ w, const float* __restrict__ bias) {
    __shared__ float plane[NL];
    __shared__ float wsum[8], wsum2[8];
    int bd = blockIdx.x;
    int d = bd % ND;
    int tid = threadIdx.x;
    const float* src = g_xconv + (size_t)bd*NL;
    for (int i = tid; i < NL; i += 256) plane[i] = src[i];
    float w9[9];
#pragma unroll
    for (int t = 0; t < 9; t++) w9[t] = w[d*9 + t];
    float bv = bias[d];
    __syncthreads();
    float* dst = g_lc + (size_t)bd*NL;
    float ls = 0.f, ls2 = 0.f;
    for (int l = tid; l < NL; l += 256) {
        int hh = l / NW, ww = l - hh*NW;
        float acc = bv;
#pragma unroll
        for (int di = 0; di < 3; di++) {
            int h2 = hh + di - 1;
            if (h2 < 0 || h2 >= NH) continue;
#pragma unroll
            for (int dj = 0; dj < 3; dj++) {
                int w2 = ww + dj - 1;
                if (w2 < 0 || w2 >= NW) continue;
                acc = fmaf(plane[h2*NW + w2], w9[di*3 + dj], acc);
            }
        }
        dst[l] = acc;
        ls += acc; ls2 += acc*acc;
    }
#pragma unroll
    for (int o = 16; o > 0; o >>= 1) {
        ls  += __shfl_xor_sync(0xffffffffu, ls,  o);
        ls2 += __shfl_xor_sync(0xffffffffu, ls2, o);
    }
    if ((tid & 31) == 0) { wsum[tid >> 5] = ls; wsum2[tid >> 5] = ls2; }
    __syncthreads();
    if (tid == 0) {
        float S = 0.f, S2 = 0.f;
        for (int i = 0; i < 8; i++) { S += wsum[i]; S2 += wsum2[i]; }
        g_psum[bd] = S; g_psum2[bd] = S2;
    }
}

// ---------------- K10: BN stats (biased var over b,h,w). 1 block, 96 thr
__global__ void k_bnstats(const float* __restrict__ gamma, const float* __restrict__ beta) {
    int d = threadIdx.x;
    if (d >= ND) return;
    float S = 0.f, S2 = 0.f;
    for (int b = 0; b < NB; b++) { S += g_psum[b*ND + d]; S2 += g_psum2[b*ND + d]; }
    float inv = 1.f / (float)(NB*NL);
    float mu = S * inv;
    float var = S2 * inv - mu*mu;
    float sc = gamma[d] * rsqrtf(var + 1e-5f);
    g_bnscale[d] = sc;
    g_bnshift[d] = beta[d] - mu*sc;
}

// ---------------- K11: BN affine + SiLU + transpose lc (b,D,L) -> lcT (b,L,D)
__global__ void k_lct() {
    __shared__ float tile[32][33];
    int b = blockIdx.z, d0 = blockIdx.y*32, l0 = blockIdx.x*32;
    int tx = threadIdx.x, ty = threadIdx.y;
    for (int r = ty; r < 32; r += 8) {
        float v = g_lc[(size_t)(b*ND + d0 + r)*NL + l0 + tx];
        v = v * g_bnscale[d0 + r] + g_bnshift[d0 + r];
        tile[r][tx] = v / (1.f + __expf(-v));
    }
    __syncthreads();
    for (int r = ty; r < 32; r += 8)
        g_lcT[((size_t)b*NL + l0 + r)*ND + d0 + tx] = tile[tx][r];
}

// ---------------- K12: LayerNorm(mamT row) + add lcT, in place. one warp per row
__global__ void k_post(const float* __restrict__ gamma, const float* __restrict__ beta) {
    int R = blockIdx.x*8 + (threadIdx.x >> 5);
    int lane = threadIdx.x & 31;
    size_t base = (size_t)R*ND;
    float v0 = g_mamT[base + lane], v1 = g_mamT[base + lane + 32], v2 = g_mamT[base + lane + 64];
    float s = v0 + v1 + v2;
#pragma unroll
    for (int o = 16; o > 0; o >>= 1) s += __shfl_xor_sync(0xffffffffu, s, o);
    float mu = s * (1.f/96.f);
    float d0 = v0 - mu, d1 = v1 - mu, d2 = v2 - mu;
    float q = d0*d0 + d1*d1 + d2*d2;
#pragma unroll
    for (int o = 16; o > 0; o >>= 1) q += __shfl_xor_sync(0xffffffffu, q, o);
    float rstd = rsqrtf(q * (1.f/96.f) + 1e-5f);
    g_mamT[base + lane]      = d0*rstd*gamma[lane]      + beta[lane]      + g_lcT[base + lane];
    g_mamT[base + lane + 32] = d1*rstd*gamma[lane + 32] + beta[lane + 32] + g_lcT[base + lane + 32];
    g_mamT[base + lane + 64] = d2*rstd*gamma[lane + 64] + beta[lane + 64] + g_lcT[base + lane + 64];
}

// ---------------- K13: transpose mamT (b,L,D) -> tT (b,D,L). grid (3,72,32)
__global__ void k_trans_mam() {
    __shared__ float tile[32][33];
    int b = blockIdx.z, l0 = blockIdx.y*32, d0 = blockIdx.x*32;
    int tx = threadIdx.x, ty = threadIdx.y;
    for (int r = ty; r < 32; r += 8)
        tile[r][tx] = g_mamT[((size_t)b*NL + l0 + r)*ND + d0 + tx];
    __syncthreads();
    for (int r = ty; r < 32; r += 8)
        g_tT[(size_t)(b*ND + d0 + r)*NL + l0 + tx] = tile[tx][r];
}

// ---------------- K14: out_proj GEMM: out[b,co,l] = sum_d W[co,d]*tT[b,d,l] + bias
__global__ void k_outproj(const float* __restrict__ w, const float* __restrict__ bias,
                          float* __restrict__ out) {
    __shared__ float shx[32*132];
    __shared__ float shw[32*96];
    int b = blockIdx.y, l0 = blockIdx.x * 128, tid = threadIdx.x;
    int tx = tid & 15, ty = tid >> 4;
    int db = ty * 6, lb = tx * 8;
    float acc[6][8];
#pragma unroll
    for (int i = 0; i < 6; i++)
#pragma unroll
        for (int j = 0; j < 8; j++) acc[i][j] = 0.f;
    for (int kc = 0; kc < ND; kc += 32) {
        for (int i = tid; i < 32*128; i += 256) {
            int cc = i >> 7, li = i & 127;
            shx[cc*132 + li] = g_tT[(size_t)(b*ND + kc + cc)*NL + l0 + li];
        }
        for (int i = tid; i < 32*96; i += 256) {
            int dloc = i % 96, cl = i / 96;
            shw[cl*96 + dloc] = w[dloc*ND + kc + cl];
        }
        __syncthreads();
        for (int c = 0; c < 32; c++) {
            float xv[8];
            const float4* xr = (const float4*)&shx[c*132 + lb];
            float4 a0 = xr[0], a1 = xr[1];
            xv[0]=a0.x; xv[1]=a0.y; xv[2]=a0.z; xv[3]=a0.w;
            xv[4]=a1.x; xv[5]=a1.y; xv[6]=a1.z; xv[7]=a1.w;
#pragma unroll
            for (int i = 0; i < 6; i++) {
                float wv = shw[c*96 + db + i];
#pragma unroll
                for (int j = 0; j < 8; j++) acc[i][j] = fmaf(wv, xv[j], acc[i][j]);
            }
        }
        __syncthreads();
    }
#pragma unroll
    for (int i = 0; i < 6; i++) {
        float bv = bias[db + i];
#pragma unroll
        for (int j = 0; j < 8; j++)
            out[(size_t)(b*ND + db + i)*NL + l0 + lb + j] = acc[i][j] + bv;
    }
}

extern "C" void kernel_launch(void* const* d_in, const int* in_sizes, int n_in,
                              void* d_out, int out_size) {
    const float* x          = (const float*)d_in[0];
    const float* in_proj_w  = (const float*)d_in[1];
    const float* in_proj_b  = (const float*)d_in[2];
    // d_in[3] skip_w, d_in[4] skip_b : provably no-op (softmax over singleton axis)
    const float* conv2d_w   = (const float*)d_in[5];
    const float* conv2d_b   = (const float*)d_in[6];
    const float* local_w    = (const float*)d_in[7];
    const float* local_b    = (const float*)d_in[8];
    const float* bn_gamma   = (const float*)d_in[9];
    const float* bn_beta    = (const float*)d_in[10];
    const float* x_proj_w   = (const float*)d_in[11];
    const float* dt_projs_w = (const float*)d_in[12];
    const float* dt_projs_b = (const float*)d_in[13];
    const float* A_logs     = (const float*)d_in[14];
    const float* Ds         = (const float*)d_in[15];
    const float* norm_gamma = (const float*)d_in[16];
    const float* norm_beta  = (const float*)d_in[17];
    const float* out_proj_w = (const float*)d_in[18];
    const float* out_proj_b = (const float*)d_in[19];
    float* out = (float*)d_out;

    k_inproj   <<<dim3(NL/128, NB), 256>>>(x, in_proj_w, in_proj_b);
    k_dwconv   <<<NB*ND, 256>>>(conv2d_w, conv2d_b);
    k_trans_xconv<<<dim3(NL/32, ND/32, NB), dim3(32, 8)>>>();
    k_sim      <<<dim3(NB, NL/64), 256>>>();
    k_sort     <<<NB, 1024>>>();
    k_prep     <<<dim3(NL/16, NB), 256>>>(x_proj_w, dt_projs_w, dt_projs_b);
    k_scan     <<<NB*NK*2, 384>>>(A_logs);
    k_combine  <<<dim3(NL/16, NB), 256>>>(Ds);
    k_localconv<<<NB*ND, 256>>>(local_w, local_b);
    k_bnstats  <<<1, ND>>>(bn_gamma, bn_beta);
    k_lct      <<<dim3(NL/32, ND/32, NB), dim3(32, 8)>>>();
    k_post     <<<NB*NL/8, 256>>>(norm_gamma, norm_beta);
    k_trans_mam<<<dim3(ND/32, NL/32, NB), dim3(32, 8)>>>();
    k_outproj  <<<dim3(NL/128, NB), 256>>>(out_proj_w, out_proj_b, out);
}

// round 4
// speedup vs baseline: 1.5478x; 1.5478x over previous
#include <cuda_runtime.h>
#include <stdint.h>
#include <math.h>

// Problem constants
#define NB 32
#define ND 96
#define NL 2304   // 48*48
#define NH 48
#define NW 48
#define NK 2
#define NN 16
#define NR 6
#define NCDB 38   // NR + 2*NN
#define CENTER 1176  // 24*48+24
#define RS 224       // scan row stride: dt[0:96] B[96:112] C[112:128] x[128:224]
#define CHK 16       // scan chunk length

// ---------------- device scratch (no allocations allowed) ----------------
__device__ float g_xfeat [NB*ND*NL];
__device__ float g_xconv [NB*ND*NL];
__device__ float g_xconvT[NB*NL*ND];
__device__ float g_sim   [NB*NL];
__device__ int   g_sortidx[NB*NL];
__device__ float g_dtbc  [(size_t)NB*NK*NL*RS];
__device__ float g_y0    [NB*NL*ND];
__device__ float g_y1    [NB*NL*ND];
__device__ float g_mamT  [NB*NL*ND];
__device__ float g_lc    [NB*ND*NL];
__device__ float g_psum  [NB*ND];
__device__ float g_psum2 [NB*ND];
__device__ float g_bnscale[ND];
__device__ float g_bnshift[ND];

__device__ __forceinline__ void cpasync16(void* dst, const void* src) {
    unsigned int d = (unsigned int)__cvta_generic_to_shared(dst);
    asm volatile("cp.async.cg.shared.global [%0], [%1], 16;\n" :: "r"(d), "l"(src));
}

// ---------------- K1: in_proj GEMM: xfeat[b,d,l] = sum_c W[d,c]*x[b,c,l] + bias[d]
__global__ void k_inproj(const float* __restrict__ x, const float* __restrict__ w,
                         const float* __restrict__ bias) {
    __shared__ float shx[32*132];
    __shared__ float shw[32*96];
    int b = blockIdx.y, l0 = blockIdx.x * 128, tid = threadIdx.x;
    int tx = tid & 15, ty = tid >> 4;
    int db = ty * 6, lb = tx * 8;
    float acc[6][8];
#pragma unroll
    for (int i = 0; i < 6; i++)
#pragma unroll
        for (int j = 0; j < 8; j++) acc[i][j] = 0.f;
    for (int kc = 0; kc < ND; kc += 32) {
        for (int i = tid; i < 32*128; i += 256) {
            int cc = i >> 7, li = i & 127;
            shx[cc*132 + li] = x[(size_t)(b*ND + kc + cc)*NL + l0 + li];
        }
        for (int i = tid; i < 32*96; i += 256) {
            int dloc = i % 96, cl = i / 96;
            shw[cl*96 + dloc] = w[dloc*ND + kc + cl];
        }
        __syncthreads();
        for (int c = 0; c < 32; c++) {
            float xv[8];
            const float4* xr = (const float4*)&shx[c*132 + lb];
            float4 a0 = xr[0], a1 = xr[1];
            xv[0]=a0.x; xv[1]=a0.y; xv[2]=a0.z; xv[3]=a0.w;
            xv[4]=a1.x; xv[5]=a1.y; xv[6]=a1.z; xv[7]=a1.w;
#pragma unroll
            for (int i = 0; i < 6; i++) {
                float wv = shw[c*96 + db + i];
#pragma unroll
                for (int j = 0; j < 8; j++) acc[i][j] = fmaf(wv, xv[j], acc[i][j]);
            }
        }
        __syncthreads();
    }
#pragma unroll
    for (int i = 0; i < 6; i++) {
        float bv = bias[db + i];
#pragma unroll
        for (int j = 0; j < 8; j++)
            g_xfeat[(size_t)(b*ND + db + i)*NL + l0 + lb + j] = acc[i][j] + bv;
    }
}

// ---------------- K2: depthwise 3x3 SAME + bias + SiLU -> g_xconv
__global__ void k_dwconv(const float* __restrict__ w, const float* __restrict__ bias) {
    __shared__ float plane[NL];
    int bd = blockIdx.x;
    int d = bd % ND;
    int tid = threadIdx.x;
    const float* src = g_xfeat + (size_t)bd*NL;
    for (int i = tid; i < NL; i += 256) plane[i] = src[i];
    float w9[9];
#pragma unroll
    for (int t = 0; t < 9; t++) w9[t] = w[d*9 + t];
    float bv = bias[d];
    __syncthreads();
    float* dst = g_xconv + (size_t)bd*NL;
    for (int l = tid; l < NL; l += 256) {
        int hh = l / NW, ww = l - hh*NW;
        float acc = bv;
#pragma unroll
        for (int di = 0; di < 3; di++) {
            int h2 = hh + di - 1;
            if (h2 < 0 || h2 >= NH) continue;
#pragma unroll
            for (int dj = 0; dj < 3; dj++) {
                int w2 = ww + dj - 1;
                if (w2 < 0 || w2 >= NW) continue;
                acc = fmaf(plane[h2*NW + w2], w9[di*3 + dj], acc);
            }
        }
        dst[l] = acc / (1.f + __expf(-acc));
    }
}

// ---------------- K3: transpose xconv (b,D,L) -> xconvT (b,L,D)
__global__ void k_trans_xconv() {
    __shared__ float tile[32][33];
    int b = blockIdx.z, d0 = blockIdx.y*32, l0 = blockIdx.x*32;
    int tx = threadIdx.x, ty = threadIdx.y;
    for (int r = ty; r < 32; r += 8)
        tile[r][tx] = g_xconv[(size_t)(b*ND + d0 + r)*NL + l0 + tx];
    __syncthreads();
    for (int r = ty; r < 32; r += 8)
        g_xconvT[((size_t)b*NL + l0 + r)*ND + d0 + tx] = tile[tx][r];
}

// ---------------- K4: cosine similarity to center pixel
__global__ void k_sim() {
    __shared__ float cf[ND];
    int b = blockIdx.x, tid = threadIdx.x;
    if (tid < ND) cf[tid] = g_xconvT[((size_t)b*NL + CENTER)*ND + tid];
    __syncthreads();
    int lane = tid & 31, wid = tid >> 5;
    float c0 = cf[lane], c1 = cf[lane+32], c2 = cf[lane+64];
    float nc = c0*c0 + c1*c1 + c2*c2;
#pragma unroll
    for (int o = 16; o > 0; o >>= 1) nc += __shfl_xor_sync(0xffffffffu, nc, o);
    float rc = 1.f / fmaxf(sqrtf(nc), 1e-12f);
    for (int r = 0; r < 8; r++) {
        int l = blockIdx.y*64 + wid*8 + r;
        const float* row = g_xconvT + ((size_t)b*NL + l)*ND;
        float x0 = row[lane], x1 = row[lane+32], x2 = row[lane+64];
        float dot = x0*c0 + x1*c1 + x2*c2;
        float nx  = x0*x0 + x1*x1 + x2*x2;
#pragma unroll
        for (int o = 16; o > 0; o >>= 1) {
            dot += __shfl_xor_sync(0xffffffffu, dot, o);
            nx  += __shfl_xor_sync(0xffffffffu, nx,  o);
        }
        if (lane == 0)
            g_sim[b*NL + l] = dot * rc / fmaxf(sqrtf(nx), 1e-12f);
    }
}

// ---------------- K5: per-batch stable argsort (desc sim, tie: idx asc). bitonic 4096
__global__ void k_sort() {
    __shared__ float sk[4096];
    __shared__ int   sv[4096];
    int b = blockIdx.x, tid = threadIdx.x;
    float ninf = -__int_as_float(0x7f800000);
    for (int i = tid; i < 4096; i += 1024) {
        sk[i] = (i < NL) ? g_sim[b*NL + i] : ninf;
        sv[i] = i;
    }
    for (int size = 2; size <= 4096; size <<= 1) {
        for (int stride = size >> 1; stride > 0; stride >>= 1) {
            __syncthreads();
            for (int t = tid; t < 2048; t += 1024) {
                int low = t & (stride - 1);
                int i = ((t - low) << 1) + low;
                int j = i + stride;
                float ki = sk[i], kj = sk[j];
                int vi = sv[i], vj = sv[j];
                bool jFirst = (kj > ki) || (kj == ki && vj < vi);
                bool up = (i & size) == 0;
                if (up ? jFirst : !jFirst) {
                    sk[i] = kj; sk[j] = ki; sv[i] = vj; sv[j] = vi;
                }
            }
        }
    }
    __syncthreads();
    for (int i = tid; i < NL; i += 1024) g_sortidx[b*NL + i] = sv[i];
}

// ---------------- K6: gather + projections -> packed rows [dt|B|C|x] stride 224
__global__ void k_prep(const float* __restrict__ xpw, const float* __restrict__ dtw,
                       const float* __restrict__ dtb) {
    __shared__ __align__(16) float s_xpw[NK*NCDB*ND];
    __shared__ float s_dtw[NK*ND*NR];
    __shared__ float s_dtb[NK*ND];
    __shared__ __align__(16) float s_x[16*ND];
    __shared__ float s_xdbl[16*NK*NCDB];
    __shared__ int s_srt[16];
    int b = blockIdx.y, p0 = blockIdx.x*16, tid = threadIdx.x;
    for (int i = tid; i < NK*NCDB*ND; i += 256) s_xpw[i] = xpw[i];
    for (int i = tid; i < NK*ND*NR;  i += 256) s_dtw[i] = dtw[i];
    for (int i = tid; i < NK*ND;     i += 256) s_dtb[i] = dtb[i];
    if (tid < 16) s_srt[tid] = g_sortidx[b*NL + p0 + tid];
    __syncthreads();
    for (int i = tid; i < 16*ND; i += 256) {
        int p = i / ND, dd = i - p*ND;
        float v = g_xconvT[((size_t)b*NL + s_srt[p])*ND + dd];
        s_x[i] = v;
        size_t row0 = ((size_t)(b*NK + 0)*NL + p0 + p)*RS;
        size_t row1 = ((size_t)(b*NK + 1)*NL + p0 + p)*RS;
        g_dtbc[row0 + 128 + dd] = v;
        g_dtbc[row1 + 128 + dd] = v;
    }
    __syncthreads();
    for (int i = tid; i < 16*NK*NCDB; i += 256) {
        int p = i / (NK*NCDB); int rem = i - p*(NK*NCDB);
        int k = rem / NCDB; int c = rem - k*NCDB;
        const float4* xr = (const float4*)&s_x[p*ND];
        const float4* wr = (const float4*)&s_xpw[(k*NCDB + c)*ND];
        float acc = 0.f;
#pragma unroll
        for (int q = 0; q < ND/4; q++) {
            float4 a = xr[q], bq = wr[q];
            acc += a.x*bq.x + a.y*bq.y + a.z*bq.z + a.w*bq.w;
        }
        s_xdbl[i] = acc;
        if (c >= NR)
            g_dtbc[(((size_t)(b*NK + k)*NL) + p0 + p)*RS + 96 + (c - NR)] = acc;
    }
    __syncthreads();
    for (int i = tid; i < 16*NK*ND; i += 256) {
        int p = i / (NK*ND); int rem = i - p*(NK*ND);
        int k = rem / ND; int dd = rem - k*ND;
        float acc = s_dtb[k*ND + dd];
        const float* xd = &s_xdbl[(p*NK + k)*NCDB];
        const float* wv = &s_dtw[(k*ND + dd)*NR];
#pragma unroll
        for (int r = 0; r < NR; r++) acc = fmaf(xd[r], wv[r], acc);
        float sp = (acc > 20.f) ? acc : log1pf(expf(acc));
        g_dtbc[(((size_t)(b*NK + k)*NL) + p0 + p)*RS + dd] = sp;
    }
}

// ---------------- K7: selective scan, double-buffered cp.async pipeline
__global__ void __launch_bounds__(384) k_scan(const float* __restrict__ A_logs,
                                              const float* __restrict__ Ds) {
    __shared__ __align__(16) float sbuf[2][CHK*RS];   // 28672 B
    __shared__ float s_y[CHK*48];                     // 3072 B
    int blk = blockIdx.x;
    int g = blk & 1, k = (blk >> 1) & 1, b = blk >> 2;
    int tid = threadIdx.x;
    int dd = tid >> 3, ng = tid & 7, n0 = ng*2;
    int d = g*48 + dd;
    float A0 = -expf(A_logs[(k*ND + d)*NN + n0]);
    float A1 = -expf(A_logs[(k*ND + d)*NN + n0 + 1]);
    float Dsum = (k == 0) ? (Ds[d] + Ds[ND + d]) : 0.f;
    float h0 = 0.f, h1 = 0.f;
    const float* base = g_dtbc + (size_t)(b*NK + k)*NL*RS;
    float* yo = ((k == 0) ? g_y0 : g_y1) + (size_t)b*NL*ND;
    const int NC = NL/CHK;   // 144

    // async-issue one chunk (16 rows x 224 floats = 896 float4)
    auto issue = [&](int c, int buf) {
        for (int i = tid; i < 896; i += 384) {
            int j = i / 56, q = i - j*56;
            int p = (k == 0) ? (c*CHK + j) : (NL - 1 - c*CHK - j);
            cpasync16(&sbuf[buf][j*RS + q*4], base + (size_t)p*RS + q*4);
        }
        asm volatile("cp.async.commit_group;\n");
    };

    issue(0, 0);
    issue(1, 1);
    for (int c = 0; c < NC; c++) {
        if (c + 1 < NC) asm volatile("cp.async.wait_group 1;\n");
        else            asm volatile("cp.async.wait_group 0;\n");
        __syncthreads();
        const float* buf = sbuf[c & 1];
#pragma unroll
        for (int j = 0; j < CHK; j++) {
            const float* r = buf + j*RS;
            float dt = r[d];
            float xv = r[128 + d];
            float B0 = r[96 + n0],  B1 = r[97 + n0];
            float C0 = r[112 + n0], C1 = r[113 + n0];
            float u = dt * xv;
            h0 = fmaf(__expf(dt*A0), h0, u*B0);
            h1 = fmaf(__expf(dt*A1), h1, u*B1);
            float yp = h0*C0 + h1*C1;
            yp += __shfl_xor_sync(0xffffffffu, yp, 4);
            yp += __shfl_xor_sync(0xffffffffu, yp, 2);
            yp += __shfl_xor_sync(0xffffffffu, yp, 1);
            if (ng == 0) s_y[j*48 + dd] = yp + Dsum*xv;
        }
        __syncthreads();
        // coalesced write-out of this chunk's y (48 d per block)
        for (int i = tid; i < CHK*48; i += 384) {
            int j = i / 48, t = i - j*48;
            int p = (k == 0) ? (c*CHK + j) : (NL - 1 - c*CHK - j);
            yo[(size_t)p*ND + g*48 + t] = s_y[i];
        }
        if (c + 2 < NC) issue(c + 2, c & 1);
    }
}

// ---------------- K8: combine fwd+rev, scatter to unsorted channel-last
__global__ void k_combine() {
    __shared__ int sidx[16];
    int b = blockIdx.y, p0 = blockIdx.x*16, tid = threadIdx.x;
    if (tid < 16) sidx[tid] = g_sortidx[b*NL + p0 + tid];
    __syncthreads();
    for (int i = tid; i < 16*ND; i += 256) {
        int pl = i / ND, d = i - pl*ND;
        size_t src = ((size_t)b*NL + p0 + pl)*ND + d;
        g_mamT[((size_t)b*NL + sidx[pl])*ND + d] = g_y0[src] + g_y1[src];
    }
}

// ---------------- K9: local conv branch: dwconv + bias, write lc, partial BN sums
__global__ void k_localconv(const float* __restrict__ w, const float* __restrict__ bias) {
    __shared__ float plane[NL];
    __shared__ float wsum[8], wsum2[8];
    int bd = blockIdx.x;
    int d = bd % ND;
    int tid = threadIdx.x;
    const float* src = g_xconv + (size_t)bd*NL;
    for (int i = tid; i < NL; i += 256) plane[i] = src[i];
    float w9[9];
#pragma unroll
    for (int t = 0; t < 9; t++) w9[t] = w[d*9 + t];
    float bv = bias[d];
    __syncthreads();
    float* dst = g_lc + (size_t)bd*NL;
    float ls = 0.f, ls2 = 0.f;
    for (int l = tid; l < NL; l += 256) {
        int hh = l / NW, ww = l - hh*NW;
        float acc = bv;
#pragma unroll
        for (int di = 0; di < 3; di++) {
            int h2 = hh + di - 1;
            if (h2 < 0 || h2 >= NH) continue;
#pragma unroll
            for (int dj = 0; dj < 3; dj++) {
                int w2 = ww + dj - 1;
                if (w2 < 0 || w2 >= NW) continue;
                acc = fmaf(plane[h2*NW + w2], w9[di*3 + dj], acc);
            }
        }
        dst[l] = acc;
        ls += acc; ls2 += acc*acc;
    }
#pragma unroll
    for (int o = 16; o > 0; o >>= 1) {
        ls  += __shfl_xor_sync(0xffffffffu, ls,  o);
        ls2 += __shfl_xor_sync(0xffffffffu, ls2, o);
    }
    if ((tid & 31) == 0) { wsum[tid >> 5] = ls; wsum2[tid >> 5] = ls2; }
    __syncthreads();
    if (tid == 0) {
        float S = 0.f, S2 = 0.f;
        for (int i = 0; i < 8; i++) { S += wsum[i]; S2 += wsum2[i]; }
        g_psum[bd] = S; g_psum2[bd] = S2;
    }
}

// ---------------- K10: BN stats
__global__ void k_bnstats(const float* __restrict__ gamma, const float* __restrict__ beta) {
    int d = threadIdx.x;
    if (d >= ND) return;
    float S = 0.f, S2 = 0.f;
    for (int b = 0; b < NB; b++) { S += g_psum[b*ND + d]; S2 += g_psum2[b*ND + d]; }
    float inv = 1.f / (float)(NB*NL);
    float mu = S * inv;
    float var = S2 * inv - mu*mu;
    float sc = gamma[d] * rsqrtf(var + 1e-5f);
    g_bnscale[d] = sc;
    g_bnshift[d] = beta[d] - mu*sc;
}

// ---------------- K11: fused LayerNorm(mamT row) + BN-affine+SiLU(lc) add, in place
__global__ void k_post(const float* __restrict__ gamma, const float* __restrict__ beta) {
    __shared__ float tile[96*33];
    int b = blockIdx.y, l0 = blockIdx.x*32, tid = threadIdx.x;
    for (int i = tid; i < 96*32; i += 256) {
        int dl = i >> 5, li = i & 31;
        float v = g_lc[(size_t)(b*ND + dl)*NL + l0 + li];
        v = v * g_bnscale[dl] + g_bnshift[dl];
        tile[dl*33 + li] = v / (1.f + __expf(-v));
    }
    __syncthreads();
    int w = tid >> 5, lane = tid & 31;
#pragma unroll
    for (int r = 0; r < 4; r++) {
        int li = w*4 + r;
        size_t base = ((size_t)b*NL + l0 + li)*ND;
        float v0 = g_mamT[base + lane], v1 = g_mamT[base + lane + 32], v2 = g_mamT[base + lane + 64];
        float s = v0 + v1 + v2;
#pragma unroll
        for (int o = 16; o > 0; o >>= 1) s += __shfl_xor_sync(0xffffffffu, s, o);
        float mu = s * (1.f/96.f);
        float d0 = v0 - mu, d1 = v1 - mu, d2 = v2 - mu;
        float q = d0*d0 + d1*d1 + d2*d2;
#pragma unroll
        for (int o = 16; o > 0; o >>= 1) q += __shfl_xor_sync(0xffffffffu, q, o);
        float rstd = rsqrtf(q * (1.f/96.f) + 1e-5f);
        g_mamT[base + lane]      = d0*rstd*gamma[lane]      + beta[lane]      + tile[lane*33 + li];
        g_mamT[base + lane + 32] = d1*rstd*gamma[lane + 32] + beta[lane + 32] + tile[(lane+32)*33 + li];
        g_mamT[base + lane + 64] = d2*rstd*gamma[lane + 64] + beta[lane + 64] + tile[(lane+64)*33 + li];
    }
}

// ---------------- K12: out_proj GEMM reading g_mamT (b,L,D) via transpose-on-load
__global__ void k_outproj(const float* __restrict__ w, const float* __restrict__ bias,
                          float* __restrict__ out) {
    __shared__ float shx[32*132];
    __shared__ float shw[32*96];
    int b = blockIdx.y, l0 = blockIdx.x * 128, tid = threadIdx.x;
    int tx = tid & 15, ty = tid >> 4;
    int db = ty * 6, lb = tx * 8;
    float acc[6][8];
#pragma unroll
    for (int i = 0; i < 6; i++)
#pragma unroll
        for (int j = 0; j < 8; j++) acc[i][j] = 0.f;
    for (int kc = 0; kc < ND; kc += 32) {
        for (int i = tid; i < 1024; i += 256) {
            int l = i >> 3, q = i & 7;
            float4 v = *(const float4*)&g_mamT[((size_t)b*NL + l0 + l)*ND + kc + q*4];
            int cl = q*4;
            shx[(cl+0)*132 + l] = v.x;
            shx[(cl+1)*132 + l] = v.y;
            shx[(cl+2)*132 + l] = v.z;
            shx[(cl+3)*132 + l] = v.w;
        }
        for (int i = tid; i < 32*96; i += 256) {
            int dloc = i % 96, cl = i / 96;
            shw[cl*96 + dloc] = w[dloc*ND + kc + cl];
        }
        __syncthreads();
        for (int c = 0; c < 32; c++) {
            float xv[8];
            const float4* xr = (const float4*)&shx[c*132 + lb];
            float4 a0 = xr[0], a1 = xr[1];
            xv[0]=a0.x; xv[1]=a0.y; xv[2]=a0.z; xv[3]=a0.w;
            xv[4]=a1.x; xv[5]=a1.y; xv[6]=a1.z; xv[7]=a1.w;
#pragma unroll
            for (int i = 0; i < 6; i++) {
                float wv = shw[c*96 + db + i];
#pragma unroll
                for (int j = 0; j < 8; j++) acc[i][j] = fmaf(wv, xv[j], acc[i][j]);
            }
        }
        __syncthreads();
    }
#pragma unroll
    for (int i = 0; i < 6; i++) {
        float bv = bias[db + i];
#pragma unroll
        for (int j = 0; j < 8; j++)
            out[(size_t)(b*ND + db + i)*NL + l0 + lb + j] = acc[i][j] + bv;
    }
}

extern "C" void kernel_launch(void* const* d_in, const int* in_sizes, int n_in,
                              void* d_out, int out_size) {
    const float* x          = (const float*)d_in[0];
    const float* in_proj_w  = (const float*)d_in[1];
    const float* in_proj_b  = (const float*)d_in[2];
    // d_in[3] skip_w, d_in[4] skip_b : provably no-op (softmax over singleton axis)
    const float* conv2d_w   = (const float*)d_in[5];
    const float* conv2d_b   = (const float*)d_in[6];
    const float* local_w    = (const float*)d_in[7];
    const float* local_b    = (const float*)d_in[8];
    const float* bn_gamma   = (const float*)d_in[9];
    const float* bn_beta    = (const float*)d_in[10];
    const float* x_proj_w   = (const float*)d_in[11];
    const float* dt_projs_w = (const float*)d_in[12];
    const float* dt_projs_b = (const float*)d_in[13];
    const float* A_logs     = (const float*)d_in[14];
    const float* Ds         = (const float*)d_in[15];
    const float* norm_gamma = (const float*)d_in[16];
    const float* norm_beta  = (const float*)d_in[17];
    const float* out_proj_w = (const float*)d_in[18];
    const float* out_proj_b = (const float*)d_in[19];
    float* out = (float*)d_out;

    k_inproj   <<<dim3(NL/128, NB), 256>>>(x, in_proj_w, in_proj_b);
    k_dwconv   <<<NB*ND, 256>>>(conv2d_w, conv2d_b);
    k_trans_xconv<<<dim3(NL/32, ND/32, NB), dim3(32, 8)>>>();
    k_sim      <<<dim3(NB, NL/64), 256>>>();
    k_sort     <<<NB, 1024>>>();
    k_prep     <<<dim3(NL/16, NB), 256>>>(x_proj_w, dt_projs_w, dt_projs_b);
    k_scan     <<<NB*NK*2, 384>>>(A_logs, Ds);
    k_combine  <<<dim3(NL/16, NB), 256>>>();
    k_localconv<<<NB*ND, 256>>>(local_w, local_b);
    k_bnstats  <<<1, ND>>>(bn_gamma, bn_beta);
    k_post     <<<dim3(NL/32, NB), 256>>>(norm_gamma, norm_beta);
    k_outproj  <<<dim3(NL/128, NB), 256>>>(out_proj_w, out_proj_b, out);
}

// round 6
// speedup vs baseline: 1.5507x; 1.0019x over previous
#include <cuda_runtime.h>
#include <stdint.h>
#include <math.h>

// Problem constants
#define NB 32
#define ND 96
#define NL 2304   // 48*48
#define NH 48
#define NW 48
#define NK 2
#define NN 16
#define NR 6
#define NCDB 38   // NR + 2*NN
#define CENTER 1176  // 24*48+24
#define RSN 352      // packed row: dt_k0[0:96] dt_k1[96:192] BC_k0[192:224] BC_k1[224:256] x[256:352]
#define CHK 16       // scan chunk length

// ---------------- device scratch (no allocations allowed) ----------------
__device__ float g_xfeat [NB*ND*NL];
__device__ float g_xconv [NB*ND*NL];
__device__ float g_xconvT[NB*NL*ND];
__device__ float g_sim   [NB*NL];
__device__ int   g_sortidx[NB*NL];
__device__ float g_dtbc  [(size_t)NB*NL*RSN];
__device__ float g_mamT  [NB*NL*ND];
__device__ float g_lc    [NB*ND*NL];
__device__ float g_psum  [NB*ND];
__device__ float g_psum2 [NB*ND];
__device__ float g_bnscale[ND];
__device__ float g_bnshift[ND];

__device__ __forceinline__ void cpasync16(void* dst, const void* src) {
    unsigned int d = (unsigned int)__cvta_generic_to_shared(dst);
    asm volatile("cp.async.cg.shared.global [%0], [%1], 16;\n" :: "r"(d), "l"(src));
}

// ---------------- K0: zero g_mamT (scan scatters with atomicAdd)
__global__ void k_zero() {
    size_t i = (size_t)blockIdx.x * blockDim.x + threadIdx.x;
    float4* p = (float4*)g_mamT;
    size_t n = (size_t)NB*NL*ND/4;
    for (; i < n; i += (size_t)gridDim.x * blockDim.x)
        p[i] = make_float4(0.f, 0.f, 0.f, 0.f);
}

// ---------------- K1: in_proj GEMM
__global__ void k_inproj(const float* __restrict__ x, const float* __restrict__ w,
                         const float* __restrict__ bias) {
    __shared__ float shx[32*132];
    __shared__ float shw[32*96];
    int b = blockIdx.y, l0 = blockIdx.x * 128, tid = threadIdx.x;
    int tx = tid & 15, ty = tid >> 4;
    int db = ty * 6, lb = tx * 8;
    float acc[6][8];
#pragma unroll
    for (int i = 0; i < 6; i++)
#pragma unroll
        for (int j = 0; j < 8; j++) acc[i][j] = 0.f;
    for (int kc = 0; kc < ND; kc += 32) {
        for (int i = tid; i < 32*128; i += 256) {
            int cc = i >> 7, li = i & 127;
            shx[cc*132 + li] = x[(size_t)(b*ND + kc + cc)*NL + l0 + li];
        }
        for (int i = tid; i < 32*96; i += 256) {
            int dloc = i % 96, cl = i / 96;
            shw[cl*96 + dloc] = w[dloc*ND + kc + cl];
        }
        __syncthreads();
        for (int c = 0; c < 32; c++) {
            float xv[8];
            const float4* xr = (const float4*)&shx[c*132 + lb];
            float4 a0 = xr[0], a1 = xr[1];
            xv[0]=a0.x; xv[1]=a0.y; xv[2]=a0.z; xv[3]=a0.w;
            xv[4]=a1.x; xv[5]=a1.y; xv[6]=a1.z; xv[7]=a1.w;
#pragma unroll
            for (int i = 0; i < 6; i++) {
                float wv = shw[c*96 + db + i];
#pragma unroll
                for (int j = 0; j < 8; j++) acc[i][j] = fmaf(wv, xv[j], acc[i][j]);
            }
        }
        __syncthreads();
    }
#pragma unroll
    for (int i = 0; i < 6; i++) {
        float bv = bias[db + i];
#pragma unroll
        for (int j = 0; j < 8; j++)
            g_xfeat[(size_t)(b*ND + db + i)*NL + l0 + lb + j] = acc[i][j] + bv;
    }
}

// ---------------- K2: depthwise 3x3 SAME + bias + SiLU -> g_xconv
__global__ void k_dwconv(const float* __restrict__ w, const float* __restrict__ bias) {
    __shared__ float plane[NL];
    int bd = blockIdx.x;
    int d = bd % ND;
    int tid = threadIdx.x;
    const float* src = g_xfeat + (size_t)bd*NL;
    for (int i = tid; i < NL; i += 256) plane[i] = src[i];
    float w9[9];
#pragma unroll
    for (int t = 0; t < 9; t++) w9[t] = w[d*9 + t];
    float bv = bias[d];
    __syncthreads();
    float* dst = g_xconv + (size_t)bd*NL;
    for (int l = tid; l < NL; l += 256) {
        int hh = l / NW, ww = l - hh*NW;
        float acc = bv;
#pragma unroll
        for (int di = 0; di < 3; di++) {
            int h2 = hh + di - 1;
            if (h2 < 0 || h2 >= NH) continue;
#pragma unroll
            for (int dj = 0; dj < 3; dj++) {
                int w2 = ww + dj - 1;
                if (w2 < 0 || w2 >= NW) continue;
                acc = fmaf(plane[h2*NW + w2], w9[di*3 + dj], acc);
            }
        }
        dst[l] = acc / (1.f + __expf(-acc));
    }
}

// ---------------- K3: transpose xconv (b,D,L) -> xconvT (b,L,D)
__global__ void k_trans_xconv() {
    __shared__ float tile[32][33];
    int b = blockIdx.z, d0 = blockIdx.y*32, l0 = blockIdx.x*32;
    int tx = threadIdx.x, ty = threadIdx.y;
    for (int r = ty; r < 32; r += 8)
        tile[r][tx] = g_xconv[(size_t)(b*ND + d0 + r)*NL + l0 + tx];
    __syncthreads();
    for (int r = ty; r < 32; r += 8)
        g_xconvT[((size_t)b*NL + l0 + r)*ND + d0 + tx] = tile[tx][r];
}

// ---------------- K4: cosine similarity to center pixel
__global__ void k_sim() {
    __shared__ float cf[ND];
    int b = blockIdx.x, tid = threadIdx.x;
    if (tid < ND) cf[tid] = g_xconvT[((size_t)b*NL + CENTER)*ND + tid];
    __syncthreads();
    int lane = tid & 31, wid = tid >> 5;
    float c0 = cf[lane], c1 = cf[lane+32], c2 = cf[lane+64];
    float nc = c0*c0 + c1*c1 + c2*c2;
#pragma unroll
    for (int o = 16; o > 0; o >>= 1) nc += __shfl_xor_sync(0xffffffffu, nc, o);
    float rc = 1.f / fmaxf(sqrtf(nc), 1e-12f);
    for (int r = 0; r < 8; r++) {
        int l = blockIdx.y*64 + wid*8 + r;
        const float* row = g_xconvT + ((size_t)b*NL + l)*ND;
        float x0 = row[lane], x1 = row[lane+32], x2 = row[lane+64];
        float dot = x0*c0 + x1*c1 + x2*c2;
        float nx  = x0*x0 + x1*x1 + x2*x2;
#pragma unroll
        for (int o = 16; o > 0; o >>= 1) {
            dot += __shfl_xor_sync(0xffffffffu, dot, o);
            nx  += __shfl_xor_sync(0xffffffffu, nx,  o);
        }
        if (lane == 0)
            g_sim[b*NL + l] = dot * rc / fmaxf(sqrtf(nx), 1e-12f);
    }
}

// ---------------- K5: per-batch stable argsort (desc sim, tie: idx asc). bitonic 4096
__global__ void k_sort() {
    __shared__ float sk[4096];
    __shared__ int   sv[4096];
    int b = blockIdx.x, tid = threadIdx.x;
    float ninf = -__int_as_float(0x7f800000);
    for (int i = tid; i < 4096; i += 1024) {
        sk[i] = (i < NL) ? g_sim[b*NL + i] : ninf;
        sv[i] = i;
    }
    for (int size = 2; size <= 4096; size <<= 1) {
        for (int stride = size >> 1; stride > 0; stride >>= 1) {
            __syncthreads();
            for (int t = tid; t < 2048; t += 1024) {
                int low = t & (stride - 1);
                int i = ((t - low) << 1) + low;
                int j = i + stride;
                float ki = sk[i], kj = sk[j];
                int vi = sv[i], vj = sv[j];
                bool jFirst = (kj > ki) || (kj == ki && vj < vi);
                bool up = (i & size) == 0;
                if (up ? jFirst : !jFirst) {
                    sk[i] = kj; sk[j] = ki; sv[i] = vj; sv[j] = vi;
                }
            }
        }
    }
    __syncthreads();
    for (int i = tid; i < NL; i += 1024) g_sortidx[b*NL + i] = sv[i];
}

// ---------------- K6: gather + projections -> packed rows stride 352
__global__ void k_prep(const float* __restrict__ xpw, const float* __restrict__ dtw,
                       const float* __restrict__ dtb) {
    __shared__ __align__(16) float s_xpw[NK*NCDB*ND];
    __shared__ float s_dtw[NK*ND*NR];
    __shared__ float s_dtb[NK*ND];
    __shared__ __align__(16) float s_x[16*ND];
    __shared__ float s_xdbl[16*NK*NCDB];
    __shared__ int s_srt[16];
    int b = blockIdx.y, p0 = blockIdx.x*16, tid = threadIdx.x;
    for (int i = tid; i < NK*NCDB*ND; i += 256) s_xpw[i] = xpw[i];
    for (int i = tid; i < NK*ND*NR;  i += 256) s_dtw[i] = dtw[i];
    for (int i = tid; i < NK*ND;     i += 256) s_dtb[i] = dtb[i];
    if (tid < 16) s_srt[tid] = g_sortidx[b*NL + p0 + tid];
    __syncthreads();
    for (int i = tid; i < 16*ND; i += 256) {
        int p = i / ND, dd = i - p*ND;
        float v = g_xconvT[((size_t)b*NL + s_srt[p])*ND + dd];
        s_x[i] = v;
        g_dtbc[((size_t)b*NL + p0 + p)*RSN + 256 + dd] = v;
    }
    __syncthreads();
    for (int i = tid; i < 16*NK*NCDB; i += 256) {
        int p = i / (NK*NCDB); int rem = i - p*(NK*NCDB);
        int k = rem / NCDB; int c = rem - k*NCDB;
        const float4* xr = (const float4*)&s_x[p*ND];
        const float4* wr = (const float4*)&s_xpw[(k*NCDB + c)*ND];
        float acc = 0.f;
#pragma unroll
        for (int q = 0; q < ND/4; q++) {
            float4 a = xr[q], bq = wr[q];
            acc += a.x*bq.x + a.y*bq.y + a.z*bq.z + a.w*bq.w;
        }
        s_xdbl[i] = acc;
        if (c >= NR)
            g_dtbc[((size_t)b*NL + p0 + p)*RSN + 192 + k*32 + (c - NR)] = acc;
    }
    __syncthreads();
    for (int i = tid; i < 16*NK*ND; i += 256) {
        int p = i / (NK*ND); int rem = i - p*(NK*ND);
        int k = rem / ND; int dd = rem - k*ND;
        float acc = s_dtb[k*ND + dd];
        const float* xd = &s_xdbl[(p*NK + k)*NCDB];
        const float* wv = &s_dtw[(k*ND + dd)*NR];
#pragma unroll
        for (int r = 0; r < NR; r++) acc = fmaf(xd[r], wv[r], acc);
        float sp = (acc > 20.f) ? acc : log1pf(expf(acc));
        g_dtbc[((size_t)b*NL + p0 + p)*RSN + k*96 + dd] = sp;
    }
}

// ---------------- K7: selective scan, 3-stage cp.async pipeline, atomic scatter out
// smem row (128 floats): dt[0:48] | B[48:64] | C[64:80] | x[80:128]
__global__ void __launch_bounds__(384) k_scan(const float* __restrict__ A_logs,
                                              const float* __restrict__ Ds) {
    __shared__ __align__(16) float sbuf[3][CHK*128];  // 24576 B
    __shared__ float s_y[2][CHK*48];                  // 6144 B
    __shared__ int s_sidx[NL];                        // 9216 B
    int blk = blockIdx.x;
    int g = blk & 1, k = (blk >> 1) & 1, b = blk >> 2;
    int tid = threadIdx.x;
    int dd = tid >> 3, ng = tid & 7, n0 = ng*2;
    int d = g*48 + dd;
    float A0 = -expf(A_logs[(k*ND + d)*NN + n0]);
    float A1 = -expf(A_logs[(k*ND + d)*NN + n0 + 1]);
    float Dsum = (k == 0) ? (Ds[d] + Ds[ND + d]) : 0.f;
    float h0 = 0.f, h1 = 0.f;
    const float* base = g_dtbc + (size_t)b*NL*RSN;
    float* mam = g_mamT + (size_t)b*NL*ND;
    const int* sidx = g_sortidx + b*NL;
    for (int i = tid; i < NL; i += 384) s_sidx[i] = sidx[i];

    const int off_dt = k*96 + g*48;
    const int off_bc = 192 + k*32;
    const int off_x  = 256 + g*48;
    const int NC = NL/CHK;   // 144

    // async-issue one chunk: 16 rows x 32 float4 (dt 12q | bc 8q | x 12q)
    auto issue = [&](int c, int buf) {
        for (int i = tid; i < 512; i += 384) {
            int j = i >> 5, q = i & 31;
            int p = (k == 0) ? (c*CHK + j) : (NL - 1 - c*CHK - j);
            const float* srow = base + (size_t)p*RSN;
            float* drow = &sbuf[buf][j*128];
            if (q < 12)      cpasync16(drow + q*4,             srow + off_dt + q*4);
            else if (q < 20) cpasync16(drow + 48 + (q-12)*4,   srow + off_bc + (q-12)*4);
            else             cpasync16(drow + 80 + (q-20)*4,   srow + off_x  + (q-20)*4);
        }
        asm volatile("cp.async.commit_group;\n");
    };

    issue(0, 0);
    issue(1, 1);
    issue(2, 2);
    for (int c = 0; c < NC; c++) {
        if (c + 2 < NC)      asm volatile("cp.async.wait_group 2;\n");
        else if (c + 1 < NC) asm volatile("cp.async.wait_group 1;\n");
        else                 asm volatile("cp.async.wait_group 0;\n");
        __syncthreads();
        const float* buf = sbuf[c % 3];
        float* ybuf = s_y[c & 1];
#pragma unroll
        for (int j = 0; j < CHK; j++) {
            const float* r = buf + j*128;
            float dt = r[dd];
            float xv = r[80 + dd];
            float B0 = r[48 + n0], B1 = r[49 + n0];
            float C0 = r[64 + n0], C1 = r[65 + n0];
            float u = dt * xv;
            h0 = fmaf(__expf(dt*A0), h0, u*B0);
            h1 = fmaf(__expf(dt*A1), h1, u*B1);
            float yp = h0*C0 + h1*C1;
            yp += __shfl_xor_sync(0xffffffffu, yp, 4);
            yp += __shfl_xor_sync(0xffffffffu, yp, 2);
            yp += __shfl_xor_sync(0xffffffffu, yp, 1);
            if (ng == 0) ybuf[j*48 + dd] = yp + Dsum*xv;
        }
        __syncthreads();
        // scatter this chunk's y to unsorted rows (2 atomic contributions/elem: k=0,k=1)
        for (int i = tid; i < CHK*48; i += 384) {
            int j = i / 48, t = i - j*48;
            int p = (k == 0) ? (c*CHK + j) : (NL - 1 - c*CHK - j);
            atomicAdd(&mam[(size_t)s_sidx[p]*ND + g*48 + t], ybuf[i]);
        }
        if (c + 3 < NC) issue(c + 3, (c + 3) % 3);
    }
}

// ---------------- K9: local conv branch: dwconv + bias, write lc, partial BN sums
__global__ void k_localconv(const float* __restrict__ w, const float* __restrict__ bias) {
    __shared__ float plane[NL];
    __shared__ float wsum[8], wsum2[8];
    int bd = blockIdx.x;
    int d = bd % ND;
    int tid = threadIdx.x;
    const float* src = g_xconv + (size_t)bd*NL;
    for (int i = tid; i < NL; i += 256) plane[i] = src[i];
    float w9[9];
#pragma unroll
    for (int t = 0; t < 9; t++) w9[t] = w[d*9 + t];
    float bv = bias[d];
    __syncthreads();
    float* dst = g_lc + (size_t)bd*NL;
    float ls = 0.f, ls2 = 0.f;
    for (int l = tid; l < NL; l += 256) {
        int hh = l / NW, ww = l - hh*NW;
        float acc = bv;
#pragma unroll
        for (int di = 0; di < 3; di++) {
            int h2 = hh + di - 1;
            if (h2 < 0 || h2 >= NH) continue;
#pragma unroll
            for (int dj = 0; dj < 3; dj++) {
                int w2 = ww + dj - 1;
                if (w2 < 0 || w2 >= NW) continue;
                acc = fmaf(plane[h2*NW + w2], w9[di*3 + dj], acc);
            }
        }
        dst[l] = acc;
        ls += acc; ls2 += acc*acc;
    }
#pragma unroll
    for (int o = 16; o > 0; o >>= 1) {
        ls  += __shfl_xor_sync(0xffffffffu, ls,  o);
        ls2 += __shfl_xor_sync(0xffffffffu, ls2, o);
    }
    if ((tid & 31) == 0) { wsum[tid >> 5] = ls; wsum2[tid >> 5] = ls2; }
    __syncthreads();
    if (tid == 0) {
        float S = 0.f, S2 = 0.f;
        for (int i = 0; i < 8; i++) { S += wsum[i]; S2 += wsum2[i]; }
        g_psum[bd] = S; g_psum2[bd] = S2;
    }
}

// ---------------- K10: BN stats
__global__ void k_bnstats(const float* __restrict__ gamma, const float* __restrict__ beta) {
    int d = threadIdx.x;
    if (d >= ND) return;
    float S = 0.f, S2 = 0.f;
    for (int b = 0; b < NB; b++) { S += g_psum[b*ND + d]; S2 += g_psum2[b*ND + d]; }
    float inv = 1.f / (float)(NB*NL);
    float mu = S * inv;
    float var = S2 * inv - mu*mu;
    float sc = gamma[d] * rsqrtf(var + 1e-5f);
    g_bnscale[d] = sc;
    g_bnshift[d] = beta[d] - mu*sc;
}

// ---------------- K11: fused LayerNorm(mamT row) + BN-affine+SiLU(lc) add, in place
__global__ void k_post(const float* __restrict__ gamma, const float* __restrict__ beta) {
    __shared__ float tile[96*33];
    int b = blockIdx.y, l0 = blockIdx.x*32, tid = threadIdx.x;
    for (int i = tid; i < 96*32; i += 256) {
        int dl = i >> 5, li = i & 31;
        float v = g_lc[(size_t)(b*ND + dl)*NL + l0 + li];
        v = v * g_bnscale[dl] + g_bnshift[dl];
        tile[dl*33 + li] = v / (1.f + __expf(-v));
    }
    __syncthreads();
    int w = tid >> 5, lane = tid & 31;
#pragma unroll
    for (int r = 0; r < 4; r++) {
        int li = w*4 + r;
        size_t base = ((size_t)b*NL + l0 + li)*ND;
        float v0 = g_mamT[base + lane], v1 = g_mamT[base + lane + 32], v2 = g_mamT[base + lane + 64];
        float s = v0 + v1 + v2;
#pragma unroll
        for (int o = 16; o > 0; o >>= 1) s += __shfl_xor_sync(0xffffffffu, s, o);
        float mu = s * (1.f/96.f);
        float d0 = v0 - mu, d1 = v1 - mu, d2 = v2 - mu;
        float q = d0*d0 + d1*d1 + d2*d2;
#pragma unroll
        for (int o = 16; o > 0; o >>= 1) q += __shfl_xor_sync(0xffffffffu, q, o);
        float rstd = rsqrtf(q * (1.f/96.f) + 1e-5f);
        g_mamT[base + lane]      = d0*rstd*gamma[lane]      + beta[lane]      + tile[lane*33 + li];
        g_mamT[base + lane + 32] = d1*rstd*gamma[lane + 32] + beta[lane + 32] + tile[(lane+32)*33 + li];
        g_mamT[base + lane + 64] = d2*rstd*gamma[lane + 64] + beta[lane + 64] + tile[(lane+64)*33 + li];
    }
}

// ---------------- K12: out_proj GEMM reading g_mamT (b,L,D) via transpose-on-load
__global__ void k_outproj(const float* __restrict__ w, const float* __restrict__ bias,
                          float* __restrict__ out) {
    __shared__ float shx[32*132];
    __shared__ float shw[32*96];
    int b = blockIdx.y, l0 = blockIdx.x * 128, tid = threadIdx.x;
    int tx = tid & 15, ty = tid >> 4;
    int db = ty * 6, lb = tx * 8;
    float acc[6][8];
#pragma unroll
    for (int i = 0; i < 6; i++)
#pragma unroll
        for (int j = 0; j < 8; j++) acc[i][j] = 0.f;
    for (int kc = 0; kc < ND; kc += 32) {
        for (int i = tid; i < 1024; i += 256) {
            int l = i >> 3, q = i & 7;
            float4 v = *(const float4*)&g_mamT[((size_t)b*NL + l0 + l)*ND + kc + q*4];
            int cl = q*4;
            shx[(cl+0)*132 + l] = v.x;
            shx[(cl+1)*132 + l] = v.y;
            shx[(cl+2)*132 + l] = v.z;
            shx[(cl+3)*132 + l] = v.w;
        }
        for (int i = tid; i < 32*96; i += 256) {
            int dloc = i % 96, cl = i / 96;
            shw[cl*96 + dloc] = w[dloc*ND + kc + cl];
        }
        __syncthreads();
        for (int c = 0; c < 32; c++) {
            float xv[8];
            const float4* xr = (const float4*)&shx[c*132 + lb];
            float4 a0 = xr[0], a1 = xr[1];
            xv[0]=a0.x; xv[1]=a0.y; xv[2]=a0.z; xv[3]=a0.w;
            xv[4]=a1.x; xv[5]=a1.y; xv[6]=a1.z; xv[7]=a1.w;
#pragma unroll
            for (int i = 0; i < 6; i++) {
                float wv = shw[c*96 + db + i];
#pragma unroll
                for (int j = 0; j < 8; j++) acc[i][j] = fmaf(wv, xv[j], acc[i][j]);
            }
        }
        __syncthreads();
    }
#pragma unroll
    for (int i = 0; i < 6; i++) {
        float bv = bias[db + i];
#pragma unroll
        for (int j = 0; j < 8; j++)
            out[(size_t)(b*ND + db + i)*NL + l0 + lb + j] = acc[i][j] + bv;
    }
}

extern "C" void kernel_launch(void* const* d_in, const int* in_sizes, int n_in,
                              void* d_out, int out_size) {
    const float* x          = (const float*)d_in[0];
    const float* in_proj_w  = (const float*)d_in[1];
    const float* in_proj_b  = (const float*)d_in[2];
    // d_in[3] skip_w, d_in[4] skip_b : provably no-op (softmax over singleton axis)
    const float* conv2d_w   = (const float*)d_in[5];
    const float* conv2d_b   = (const float*)d_in[6];
    const float* local_w    = (const float*)d_in[7];
    const float* local_b    = (const float*)d_in[8];
    const float* bn_gamma   = (const float*)d_in[9];
    const float* bn_beta    = (const float*)d_in[10];
    const float* x_proj_w   = (const float*)d_in[11];
    const float* dt_projs_w = (const float*)d_in[12];
    const float* dt_projs_b = (const float*)d_in[13];
    const float* A_logs     = (const float*)d_in[14];
    const float* Ds         = (const float*)d_in[15];
    const float* norm_gamma = (const float*)d_in[16];
    const float* norm_beta  = (const float*)d_in[17];
    const float* out_proj_w = (const float*)d_in[18];
    const float* out_proj_b = (const float*)d_in[19];
    float* out = (float*)d_out;

    k_zero     <<<1728, 256>>>();
    k_inproj   <<<dim3(NL/128, NB), 256>>>(x, in_proj_w, in_proj_b);
    k_dwconv   <<<NB*ND, 256>>>(conv2d_w, conv2d_b);
    k_trans_xconv<<<dim3(NL/32, ND/32, NB), dim3(32, 8)>>>();
    k_sim      <<<dim3(NB, NL/64), 256>>>();
    k_sort     <<<NB, 1024>>>();
    k_prep     <<<dim3(NL/16, NB), 256>>>(x_proj_w, dt_projs_w, dt_projs_b);
    k_scan     <<<NB*NK*2, 384>>>(A_logs, Ds);
    k_localconv<<<NB*ND, 256>>>(local_w, local_b);
    k_bnstats  <<<1, ND>>>(bn_gamma, bn_beta);
    k_post     <<<dim3(NL/32, NB), 256>>>(norm_gamma, norm_beta);
    k_outproj  <<<dim3(NL/128, NB), 256>>>(out_proj_w, out_proj_b, out);
}